// round 14
// baseline (speedup 1.0000x reference)
#include <cuda_runtime.h>
#include <cuda_bf16.h>
#include <math.h>
#include <stdint.h>

// MatrixMLP R14: two-kernel split.
//   Kernel A: R12's best config (one-shot, lb(256,2), static-index fp64 pinv).
//   Kernel B: restructured to ONE m16 tile per warp (16 samples) -> shorter
//             MMA dependency chains, ~100 regs, lb(128,5) -> 5 CTAs/SM.

#define NTHREADS 128
#define TILE_B 64            // samples per CTA iteration (16 per warp)
#define B_MAX 524288
#define RCOND2 2.2737367544323206e-11   // (40*2^-23)^2, JAX pinv fp32 4x4

__device__ float4 g_xls[B_MAX];          // kernel A -> kernel B scratch

// ---- smem layout for kernel B (bytes from dynamic base) ----
#define O_W1F 0            // 48 frags * 64 u32 tf32        (12288 B)
#define O_W2F 12288        // 64 frags * 64 u32 bf16x2      (16384 B)
#define O_B1P 28672        // 512 float2                    (4096 B)
#define O_B2P 32768        // 256 float2                    (2048 B)
#define O_W3F 34816        // 4 frags * 64 u32 bf16x2       (1024 B)
#define O_B3  35840        // float4 (+pad)
#define O_XLS 35872        // 4 warps * 32 * float4         (2048 B; rows 0..15 used)
#define SMEM_DYN 37920

__device__ __forceinline__ uint32_t f2tf(float f) {
    uint32_t r;
    asm("cvt.rna.tf32.f32 %0, %1;" : "=r"(r) : "f"(f));
    return r;
}
__device__ __forceinline__ uint32_t packbf(float lo, float hi) {
    uint32_t r;
    asm("cvt.rn.bf16x2.f32 %0, %1, %2;" : "=r"(r) : "f"(hi), "f"(lo));
    return r;
}
__device__ __forceinline__ void mma_tf32(float* c, const uint32_t* a,
                                         uint32_t b0, uint32_t b1) {
    asm volatile(
        "mma.sync.aligned.m16n8k8.row.col.f32.tf32.tf32.f32 "
        "{%0,%1,%2,%3}, {%4,%5,%6,%7}, {%8,%9}, {%0,%1,%2,%3};"
        : "+f"(c[0]), "+f"(c[1]), "+f"(c[2]), "+f"(c[3])
        : "r"(a[0]), "r"(a[1]), "r"(a[2]), "r"(a[3]), "r"(b0), "r"(b1));
}
__device__ __forceinline__ void mma_bf16(float* c, const uint32_t* a,
                                         uint32_t b0, uint32_t b1) {
    asm volatile(
        "mma.sync.aligned.m16n8k16.row.col.f32.bf16.bf16.f32 "
        "{%0,%1,%2,%3}, {%4,%5,%6,%7}, {%8,%9}, {%0,%1,%2,%3};"
        : "+f"(c[0]), "+f"(c[1]), "+f"(c[2]), "+f"(c[3])
        : "r"(a[0]), "r"(a[1]), "r"(a[2]), "r"(a[3]), "r"(b0), "r"(b1));
}

// ---- rare-path fp64 Jacobi SVD pinv, register-resident (static indices) ----
#define JROT(p, q) do {                                                      \
    double apq = A[p][q];                                                    \
    if (fabs(apq) > 1e-300) {                                                \
        double tau = (A[q][q] - A[p][p]) / (2.0 * apq);                      \
        double t = ((tau >= 0.0) ? 1.0 : -1.0) /                             \
                   (fabs(tau) + sqrt(1.0 + tau * tau));                      \
        double cc = 1.0 / sqrt(1.0 + t * t);                                 \
        double ss = t * cc;                                                  \
        _Pragma("unroll")                                                    \
        for (int k = 0; k < 4; k++) {                                        \
            double akp = A[k][p], akq = A[k][q];                             \
            A[k][p] = cc * akp - ss * akq;                                   \
            A[k][q] = ss * akp + cc * akq;                                   \
        }                                                                    \
        _Pragma("unroll")                                                    \
        for (int k = 0; k < 4; k++) {                                        \
            double apk = A[p][k], aqk = A[q][k];                             \
            A[p][k] = cc * apk - ss * aqk;                                   \
            A[q][k] = ss * apk + cc * aqk;                                   \
        }                                                                    \
        _Pragma("unroll")                                                    \
        for (int k = 0; k < 4; k++) {                                        \
            double vkp = V[k][p], vkq = V[k][q];                             \
            V[k][p] = cc * vkp - ss * vkq;                                   \
            V[k][q] = ss * vkp + cc * vkq;                                   \
        }                                                                    \
    }                                                                        \
} while (0)

__device__ __noinline__ void pinv_slow(const float* a, const float* yv, float* xout)
{
    double A[4][4], V[4][4];
#pragma unroll
    for (int i = 0; i < 4; i++)
#pragma unroll
        for (int j = 0; j < 4; j++) {
            double s = 0.0;
#pragma unroll
            for (int r = 0; r < 4; r++)
                s += (double)a[r * 4 + i] * (double)a[r * 4 + j];
            A[i][j] = s;
            V[i][j] = (i == j) ? 1.0 : 0.0;
        }

    double z[4];
#pragma unroll
    for (int i = 0; i < 4; i++) {
        double s = 0.0;
#pragma unroll
        for (int r = 0; r < 4; r++)
            s += (double)a[r * 4 + i] * (double)yv[r];
        z[i] = s;
    }

#pragma unroll
    for (int sweep = 0; sweep < 4; sweep++) {
        JROT(0, 1); JROT(0, 2); JROT(0, 3);
        JROT(1, 2); JROT(1, 3); JROT(2, 3);
    }

    double lam[4], lmax = 0.0;
#pragma unroll
    for (int i = 0; i < 4; i++) {
        lam[i] = A[i][i];
        if (lam[i] > lmax) lmax = lam[i];
    }
    const double thr = RCOND2 * lmax;

    double w[4];
#pragma unroll
    for (int i = 0; i < 4; i++) {
        double s = 0.0;
#pragma unroll
        for (int k = 0; k < 4; k++) s += V[k][i] * z[k];
        w[i] = (lam[i] > thr) ? (s / lam[i]) : 0.0;
    }
#pragma unroll
    for (int j = 0; j < 4; j++) {
        double s = 0.0;
#pragma unroll
        for (int i = 0; i < 4; i++) s += V[j][i] * w[i];
        xout[j] = (float)s;
    }
}

// ================= Kernel A: x_ls (R12 best config) =================
__global__ __launch_bounds__(256, 2)
void xls_kernel(const float* __restrict__ x, int nsamples)
{
    const int i = blockIdx.x * 256 + threadIdx.x;
    if (i >= nsamples) return;

    const float4* xp = (const float4*)x + (size_t)i * 5;
    const float4 f0 = xp[0], f1 = xp[1], f2 = xp[2], f3 = xp[3], f4 = xp[4];

    const float a00 = f0.x, a01 = f1.x, a02 = f2.x, a03 = f3.x;
    const float a10 = f0.y, a11 = f1.y, a12 = f2.y, a13 = f3.y;
    const float a20 = f0.z, a21 = f1.z, a22 = f2.z, a23 = f3.z;
    const float a30 = f0.w, a31 = f1.w, a32 = f2.w, a33 = f3.w;

    const float s0 = a00 * a11 - a01 * a10;
    const float s1 = a00 * a12 - a02 * a10;
    const float s2 = a00 * a13 - a03 * a10;
    const float s3 = a01 * a12 - a02 * a11;
    const float s4 = a01 * a13 - a03 * a11;
    const float s5 = a02 * a13 - a03 * a12;
    const float c5 = a22 * a33 - a23 * a32;
    const float c4 = a21 * a33 - a23 * a31;
    const float c3 = a21 * a32 - a22 * a31;
    const float c2 = a20 * a33 - a23 * a30;
    const float c1 = a20 * a32 - a22 * a30;
    const float c0 = a20 * a31 - a21 * a30;
    const float det = s0*c5 - s1*c4 + s2*c3 + s3*c2 - s4*c1 + s5*c0;
    const float y0 = f4.x, y1 = f4.y, y2 = f4.z, y3 = f4.w;

    const float F2 =
        a00*a00+a01*a01+a02*a02+a03*a03 + a10*a10+a11*a11+a12*a12+a13*a13 +
        a20*a20+a21*a21+a22*a22+a23*a23 + a30*a30+a31*a31+a32*a32+a33*a33;

    float v0, v1, v2, v3;
    if (fabsf(det) > 6e-6f * F2 * F2) {
        const float iv = 1.0f / det;
        v0 = (( a11*c5 - a12*c4 + a13*c3)*y0 + (-a01*c5 + a02*c4 - a03*c3)*y1 +
              ( a31*s5 - a32*s4 + a33*s3)*y2 + (-a21*s5 + a22*s4 - a23*s3)*y3) * iv;
        v1 = ((-a10*c5 + a12*c2 - a13*c1)*y0 + ( a00*c5 - a02*c2 + a03*c1)*y1 +
              (-a30*s5 + a32*s2 - a33*s1)*y2 + ( a20*s5 - a22*s2 + a23*s1)*y3) * iv;
        v2 = (( a10*c4 - a11*c2 + a13*c0)*y0 + (-a00*c4 + a01*c2 - a03*c0)*y1 +
              ( a30*s4 - a31*s2 + a33*s0)*y2 + (-a20*s4 + a21*s2 - a23*s0)*y3) * iv;
        v3 = ((-a10*c3 + a11*c1 - a12*c0)*y0 + ( a00*c3 - a01*c1 + a02*c0)*y1 +
              (-a30*s3 + a31*s1 - a32*s0)*y2 + ( a20*s3 - a21*s1 + a22*s0)*y3) * iv;
    } else {
        float hm[16], yv[4], xo[4];
        hm[0]=a00; hm[1]=a01; hm[2]=a02; hm[3]=a03;
        hm[4]=a10; hm[5]=a11; hm[6]=a12; hm[7]=a13;
        hm[8]=a20; hm[9]=a21; hm[10]=a22; hm[11]=a23;
        hm[12]=a30; hm[13]=a31; hm[14]=a32; hm[15]=a33;
        yv[0]=y0; yv[1]=y1; yv[2]=y2; yv[3]=y3;
        pinv_slow(hm, yv, xo);
        v0=xo[0]; v1=xo[1]; v2=xo[2]; v3=xo[3];
    }
    g_xls[i] = make_float4(__saturatef(v0), __saturatef(v1),
                           __saturatef(v2), __saturatef(v3));
}

// ================= Kernel B: MLP on MMA, 1 m16-tile per warp =================
__global__ __launch_bounds__(NTHREADS, 5)
void matrixmlp_hmma(const float* __restrict__ x,
                    const float* __restrict__ W1, const float* __restrict__ b1,
                    const float* __restrict__ W2, const float* __restrict__ b2,
                    const float* __restrict__ W3, const float* __restrict__ b3,
                    float* __restrict__ out, int ntiles)
{
    extern __shared__ char sm[];
    uint32_t* w1f = (uint32_t*)(sm + O_W1F);
    uint32_t* w2f = (uint32_t*)(sm + O_W2F);
    float2*   b1p = (float2*)(sm + O_B1P);
    float2*   b2p = (float2*)(sm + O_B2P);
    uint32_t* w3f = (uint32_t*)(sm + O_W3F);
    float4*   b3s = (float4*)(sm + O_B3);

    const int tid  = threadIdx.x;
    const int lane = tid & 31;
    const int wid  = tid >> 5;
    const int q    = lane & 3;
    const int g    = lane >> 2;

    float* xls = (float*)(sm + O_XLS + wid * 512);         // rows 0..15 used

    // ---- stage weights ----
    for (int i = tid; i < 3072; i += NTHREADS) {           // W1 tf32 k8 frags
        int e = i & 1, ln = (i >> 1) & 31, fi = i >> 6;
        int kt = fi >> 4, nt = fi & 15;
        int kk = 8 * kt + (ln & 3) + 4 * e, nn = 8 * nt + (ln >> 2);
        w1f[(fi << 6) + ((ln << 1) | e)] = f2tf(W1[kk * 128 + nn]);
    }
    for (int i = tid; i < 4096; i += NTHREADS) {           // W2 bf16 k16 frags
        int e = i & 1, ln = (i >> 1) & 31, fi = i >> 6;
        int kt = fi >> 3, nt = fi & 7;
        int k0 = 16 * kt + 2 * (ln & 3) + 8 * e, nn = 8 * nt + (ln >> 2);
        w2f[(fi << 6) + ((ln << 1) | e)] =
            packbf(W2[k0 * 64 + nn], W2[(k0 + 1) * 64 + nn]);
    }
    for (int i = tid; i < 256; i += NTHREADS) {            // W3 bf16 k16 frags (N=8 pad)
        int e = i & 1, ln = (i >> 1) & 31, fi = i >> 6;
        int k0 = 16 * fi + 2 * (ln & 3) + 8 * e, nn = ln >> 2;
        float lo = (nn < 4) ? W3[k0 * 4 + nn] : 0.0f;
        float hi = (nn < 4) ? W3[(k0 + 1) * 4 + nn] : 0.0f;
        w3f[(fi << 6) + ((ln << 1) | e)] = packbf(lo, hi);
    }
    for (int i = tid; i < 512; i += NTHREADS) {            // b1 pairs
        int ln = i & 31, ntg = i >> 5, qq = ln & 3;
        b1p[i] = make_float2(b1[8 * ntg + 2 * qq], b1[8 * ntg + 2 * qq + 1]);
    }
    for (int i = tid; i < 256; i += NTHREADS) {            // b2 pairs
        int ln = i & 31, nt = i >> 5, qq = ln & 3;
        b2p[i] = make_float2(b2[8 * nt + 2 * qq], b2[8 * nt + 2 * qq + 1]);
    }
    if (tid == 0) *b3s = *(const float4*)b3;
    __syncthreads();

    const float4 b3r = *b3s;

    for (int tile = blockIdx.x; tile < ntiles; tile += gridDim.x) {
        const int base16 = tile * TILE_B + wid * 16;       // this warp's 16 samples

        // ---- x_ls: lanes 0..15 fetch, stage in smem ----
        if (lane < 16) {
            *(float4*)&xls[lane * 4] = g_xls[base16 + lane];
        }
        __syncwarp();

        // ---- A0 tf32 fragments [3 Ktiles][4], single m16 tile ----
        const float* xg = x + (size_t)base16 * 20;
        uint32_t A0[3][4];
        {
            const int r0 = g, r1 = g + 8;
#pragma unroll
            for (int kt = 0; kt < 2; kt++) {
                A0[kt][0] = f2tf(xg[r0 * 20 + 8 * kt + q]);
                A0[kt][1] = f2tf(xg[r1 * 20 + 8 * kt + q]);
                A0[kt][2] = f2tf(xg[r0 * 20 + 8 * kt + q + 4]);
                A0[kt][3] = f2tf(xg[r1 * 20 + 8 * kt + q + 4]);
            }
            A0[2][0] = f2tf(xg[r0 * 20 + 16 + q]);
            A0[2][1] = f2tf(xg[r1 * 20 + 16 + q]);
            A0[2][2] = f2tf(xls[r0 * 4 + q]);
            A0[2][3] = f2tf(xls[r1 * 4 + q]);
        }
        __syncwarp();

        // ---- layers 1+2: tf32 MMA -> in-register bf16 A-frag -> bf16 MMA ----
        float C2[8][4];
#pragma unroll
        for (int nt = 0; nt < 8; nt++) {
            const float2 bb = b2p[nt * 32 + lane];
            C2[nt][0] = bb.x; C2[nt][1] = bb.y;
            C2[nt][2] = bb.x; C2[nt][3] = bb.y;
        }

#pragma unroll 1
        for (int c = 0; c < 8; c++) {
            const float2 bb0 = b1p[(2 * c) * 32 + lane];
            const float2 bb1 = b1p[(2 * c + 1) * 32 + lane];
            float C1[2][4];
            C1[0][0] = bb0.x; C1[0][1] = bb0.y;
            C1[0][2] = bb0.x; C1[0][3] = bb0.y;
            C1[1][0] = bb1.x; C1[1][1] = bb1.y;
            C1[1][2] = bb1.x; C1[1][3] = bb1.y;

#pragma unroll
            for (int kt = 0; kt < 3; kt++) {
#pragma unroll
                for (int t = 0; t < 2; t++) {
                    uint2 b = *(const uint2*)
                        &w1f[((kt * 16 + 2 * c + t) << 6) + (lane << 1)];
                    mma_tf32(C1[t], A0[kt], b.x, b.y);
                }
            }

            uint32_t af[4];
            af[0] = packbf(fmaxf(C1[0][0], 0.0f), fmaxf(C1[0][1], 0.0f));
            af[1] = packbf(fmaxf(C1[0][2], 0.0f), fmaxf(C1[0][3], 0.0f));
            af[2] = packbf(fmaxf(C1[1][0], 0.0f), fmaxf(C1[1][1], 0.0f));
            af[3] = packbf(fmaxf(C1[1][2], 0.0f), fmaxf(C1[1][3], 0.0f));

#pragma unroll
            for (int nt = 0; nt < 8; nt++) {
                uint2 b = *(const uint2*)&w2f[((c * 8 + nt) << 6) + (lane << 1)];
                mma_bf16(C2[nt], af, b.x, b.y);
            }
        }

        // ---- layer3 on MMA: relu(C2) -> bf16 A-frags -> m16n8k16, N=8 pad ----
        float C3[4];
#pragma unroll
        for (int r = 0; r < 4; r++) C3[r] = 0.0f;

#pragma unroll
        for (int kt = 0; kt < 4; kt++) {
            uint32_t a3[4];
            a3[0] = packbf(fmaxf(C2[2 * kt][0], 0.0f), fmaxf(C2[2 * kt][1], 0.0f));
            a3[1] = packbf(fmaxf(C2[2 * kt][2], 0.0f), fmaxf(C2[2 * kt][3], 0.0f));
            a3[2] = packbf(fmaxf(C2[2 * kt + 1][0], 0.0f), fmaxf(C2[2 * kt + 1][1], 0.0f));
            a3[3] = packbf(fmaxf(C2[2 * kt + 1][2], 0.0f), fmaxf(C2[2 * kt + 1][3], 0.0f));
            uint2 b = *(const uint2*)&w3f[(kt << 6) + (lane << 1)];
            mma_bf16(C3, a3, b.x, b.y);
        }

        // ---- epilogue: q<2 lanes hold real cols (2q, 2q+1 of 0..3) ----
        if (q < 2) {
            const float b3a = (q == 0) ? b3r.x : b3r.z;
            const float b3b = (q == 0) ? b3r.y : b3r.w;
            const int rA = g, rB = g + 8;
            const float2 xA = *(const float2*)&xls[rA * 4 + 2 * q];
            float2 oA;
            oA.x = __saturatef(xA.x + C3[0] + b3a);
            oA.y = __saturatef(xA.y + C3[1] + b3b);
            ((float2*)out)[(size_t)(base16 + rA) * 2 + q] = oA;
            const float2 xB = *(const float2*)&xls[rB * 4 + 2 * q];
            float2 oB;
            oB.x = __saturatef(xB.x + C3[2] + b3a);
            oB.y = __saturatef(xB.y + C3[3] + b3b);
            ((float2*)out)[(size_t)(base16 + rB) * 2 + q] = oB;
        }
        __syncwarp();   // xls reads done before next iteration overwrites
    }
}

extern "C" void kernel_launch(void* const* d_in, const int* in_sizes, int n_in,
                              void* d_out, int out_size)
{
    const float* x  = (const float*)d_in[0];
    const float* W1 = (const float*)d_in[1];
    const float* b1 = (const float*)d_in[2];
    const float* W2 = (const float*)d_in[3];
    const float* b2 = (const float*)d_in[4];
    const float* W3 = (const float*)d_in[5];
    const float* b3 = (const float*)d_in[6];
    float* out = (float*)d_out;

    const int nsamples = in_sizes[0] / 20;
    const int ntiles = nsamples / TILE_B;        // 8192

    // Kernel A: x_ls into scratch (R12 best config)
    xls_kernel<<<(nsamples + 255) / 256, 256>>>(x, nsamples);

    // Kernel B: MLP, 5 CTAs/SM persistent
    int grid = 5 * 148;
    if (grid > ntiles) grid = ntiles;
    cudaFuncSetAttribute(matrixmlp_hmma,
                         cudaFuncAttributeMaxDynamicSharedMemorySize, SMEM_DYN);
    matrixmlp_hmma<<<grid, NTHREADS, SMEM_DYN>>>(x, W1, b1, W2, b2, W3, b3, out, ntiles);
}

// round 15
// speedup vs baseline: 1.0854x; 1.0854x over previous
#include <cuda_runtime.h>
#include <cuda_bf16.h>
#include <math.h>
#include <stdint.h>

// MatrixMLP R15: two-kernel split (R12 base — best measured 96.4us).
//   Kernel A: one-shot x_ls, lb(256,2), static-index fp64 Jacobi pinv.
//   Kernel B: 2 M-tiles/warp MMA MLP; SINGLE CHANGE vs R12: chunk loop
//             unrolled 2x to overlap chunk c's layer2 MMAs with chunk
//             c+1's independent layer1 chain.

#define NTHREADS 128
#define TILE 128
#define B_MAX 524288
#define RCOND2 2.2737367544323206e-11   // (40*2^-23)^2, JAX pinv fp32 4x4

__device__ float4 g_xls[B_MAX];          // kernel A -> kernel B scratch

// ---- smem layout for kernel B (bytes from dynamic base) ----
#define O_W1F 0            // 48 frags * 64 u32 tf32        (12288 B)
#define O_W2F 12288        // 64 frags * 64 u32 bf16x2      (16384 B)
#define O_B1P 28672        // 512 float2                    (4096 B)
#define O_B2P 32768        // 256 float2                    (2048 B)
#define O_W3F 34816        // 4 frags * 64 u32 bf16x2       (1024 B)
#define O_B3  35840        // float4 (+pad)
#define O_XLS 35872        // 4 warps * 32 * float4         (2048 B)
#define SMEM_DYN 37920

__device__ __forceinline__ uint32_t f2tf(float f) {
    uint32_t r;
    asm("cvt.rna.tf32.f32 %0, %1;" : "=r"(r) : "f"(f));
    return r;
}
__device__ __forceinline__ uint32_t packbf(float lo, float hi) {
    uint32_t r;
    asm("cvt.rn.bf16x2.f32 %0, %1, %2;" : "=r"(r) : "f"(hi), "f"(lo));
    return r;
}
__device__ __forceinline__ void mma_tf32(float* c, const uint32_t* a,
                                         uint32_t b0, uint32_t b1) {
    asm volatile(
        "mma.sync.aligned.m16n8k8.row.col.f32.tf32.tf32.f32 "
        "{%0,%1,%2,%3}, {%4,%5,%6,%7}, {%8,%9}, {%0,%1,%2,%3};"
        : "+f"(c[0]), "+f"(c[1]), "+f"(c[2]), "+f"(c[3])
        : "r"(a[0]), "r"(a[1]), "r"(a[2]), "r"(a[3]), "r"(b0), "r"(b1));
}
__device__ __forceinline__ void mma_bf16(float* c, const uint32_t* a,
                                         uint32_t b0, uint32_t b1) {
    asm volatile(
        "mma.sync.aligned.m16n8k16.row.col.f32.bf16.bf16.f32 "
        "{%0,%1,%2,%3}, {%4,%5,%6,%7}, {%8,%9}, {%0,%1,%2,%3};"
        : "+f"(c[0]), "+f"(c[1]), "+f"(c[2]), "+f"(c[3])
        : "r"(a[0]), "r"(a[1]), "r"(a[2]), "r"(a[3]), "r"(b0), "r"(b1));
}

// ---- rare-path fp64 Jacobi SVD pinv, register-resident (static indices) ----
#define JROT(p, q) do {                                                      \
    double apq = A[p][q];                                                    \
    if (fabs(apq) > 1e-300) {                                                \
        double tau = (A[q][q] - A[p][p]) / (2.0 * apq);                      \
        double t = ((tau >= 0.0) ? 1.0 : -1.0) /                             \
                   (fabs(tau) + sqrt(1.0 + tau * tau));                      \
        double cc = 1.0 / sqrt(1.0 + t * t);                                 \
        double ss = t * cc;                                                  \
        _Pragma("unroll")                                                    \
        for (int k = 0; k < 4; k++) {                                        \
            double akp = A[k][p], akq = A[k][q];                             \
            A[k][p] = cc * akp - ss * akq;                                   \
            A[k][q] = ss * akp + cc * akq;                                   \
        }                                                                    \
        _Pragma("unroll")                                                    \
        for (int k = 0; k < 4; k++) {                                        \
            double apk = A[p][k], aqk = A[q][k];                             \
            A[p][k] = cc * apk - ss * aqk;                                   \
            A[q][k] = ss * apk + cc * aqk;                                   \
        }                                                                    \
        _Pragma("unroll")                                                    \
        for (int k = 0; k < 4; k++) {                                        \
            double vkp = V[k][p], vkq = V[k][q];                             \
            V[k][p] = cc * vkp - ss * vkq;                                   \
            V[k][q] = ss * vkp + cc * vkq;                                   \
        }                                                                    \
    }                                                                        \
} while (0)

__device__ __noinline__ void pinv_slow(const float* a, const float* yv, float* xout)
{
    double A[4][4], V[4][4];
#pragma unroll
    for (int i = 0; i < 4; i++)
#pragma unroll
        for (int j = 0; j < 4; j++) {
            double s = 0.0;
#pragma unroll
            for (int r = 0; r < 4; r++)
                s += (double)a[r * 4 + i] * (double)a[r * 4 + j];
            A[i][j] = s;
            V[i][j] = (i == j) ? 1.0 : 0.0;
        }

    double z[4];
#pragma unroll
    for (int i = 0; i < 4; i++) {
        double s = 0.0;
#pragma unroll
        for (int r = 0; r < 4; r++)
            s += (double)a[r * 4 + i] * (double)yv[r];
        z[i] = s;
    }

#pragma unroll
    for (int sweep = 0; sweep < 4; sweep++) {
        JROT(0, 1); JROT(0, 2); JROT(0, 3);
        JROT(1, 2); JROT(1, 3); JROT(2, 3);
    }

    double lam[4], lmax = 0.0;
#pragma unroll
    for (int i = 0; i < 4; i++) {
        lam[i] = A[i][i];
        if (lam[i] > lmax) lmax = lam[i];
    }
    const double thr = RCOND2 * lmax;

    double w[4];
#pragma unroll
    for (int i = 0; i < 4; i++) {
        double s = 0.0;
#pragma unroll
        for (int k = 0; k < 4; k++) s += V[k][i] * z[k];
        w[i] = (lam[i] > thr) ? (s / lam[i]) : 0.0;
    }
#pragma unroll
    for (int j = 0; j < 4; j++) {
        double s = 0.0;
#pragma unroll
        for (int i = 0; i < 4; i++) s += V[j][i] * w[i];
        xout[j] = (float)s;
    }
}

// ================= Kernel A: x_ls (R12 best config) =================
__global__ __launch_bounds__(256, 2)
void xls_kernel(const float* __restrict__ x, int nsamples)
{
    const int i = blockIdx.x * 256 + threadIdx.x;
    if (i >= nsamples) return;

    const float4* xp = (const float4*)x + (size_t)i * 5;
    const float4 f0 = xp[0], f1 = xp[1], f2 = xp[2], f3 = xp[3], f4 = xp[4];

    const float a00 = f0.x, a01 = f1.x, a02 = f2.x, a03 = f3.x;
    const float a10 = f0.y, a11 = f1.y, a12 = f2.y, a13 = f3.y;
    const float a20 = f0.z, a21 = f1.z, a22 = f2.z, a23 = f3.z;
    const float a30 = f0.w, a31 = f1.w, a32 = f2.w, a33 = f3.w;

    const float s0 = a00 * a11 - a01 * a10;
    const float s1 = a00 * a12 - a02 * a10;
    const float s2 = a00 * a13 - a03 * a10;
    const float s3 = a01 * a12 - a02 * a11;
    const float s4 = a01 * a13 - a03 * a11;
    const float s5 = a02 * a13 - a03 * a12;
    const float c5 = a22 * a33 - a23 * a32;
    const float c4 = a21 * a33 - a23 * a31;
    const float c3 = a21 * a32 - a22 * a31;
    const float c2 = a20 * a33 - a23 * a30;
    const float c1 = a20 * a32 - a22 * a30;
    const float c0 = a20 * a31 - a21 * a30;
    const float det = s0*c5 - s1*c4 + s2*c3 + s3*c2 - s4*c1 + s5*c0;
    const float y0 = f4.x, y1 = f4.y, y2 = f4.z, y3 = f4.w;

    const float F2 =
        a00*a00+a01*a01+a02*a02+a03*a03 + a10*a10+a11*a11+a12*a12+a13*a13 +
        a20*a20+a21*a21+a22*a22+a23*a23 + a30*a30+a31*a31+a32*a32+a33*a33;

    float v0, v1, v2, v3;
    if (fabsf(det) > 6e-6f * F2 * F2) {
        const float iv = 1.0f / det;
        v0 = (( a11*c5 - a12*c4 + a13*c3)*y0 + (-a01*c5 + a02*c4 - a03*c3)*y1 +
              ( a31*s5 - a32*s4 + a33*s3)*y2 + (-a21*s5 + a22*s4 - a23*s3)*y3) * iv;
        v1 = ((-a10*c5 + a12*c2 - a13*c1)*y0 + ( a00*c5 - a02*c2 + a03*c1)*y1 +
              (-a30*s5 + a32*s2 - a33*s1)*y2 + ( a20*s5 - a22*s2 + a23*s1)*y3) * iv;
        v2 = (( a10*c4 - a11*c2 + a13*c0)*y0 + (-a00*c4 + a01*c2 - a03*c0)*y1 +
              ( a30*s4 - a31*s2 + a33*s0)*y2 + (-a20*s4 + a21*s2 - a23*s0)*y3) * iv;
        v3 = ((-a10*c3 + a11*c1 - a12*c0)*y0 + ( a00*c3 - a01*c1 + a02*c0)*y1 +
              (-a30*s3 + a31*s1 - a32*s0)*y2 + ( a20*s3 - a21*s1 + a22*s0)*y3) * iv;
    } else {
        float hm[16], yv[4], xo[4];
        hm[0]=a00; hm[1]=a01; hm[2]=a02; hm[3]=a03;
        hm[4]=a10; hm[5]=a11; hm[6]=a12; hm[7]=a13;
        hm[8]=a20; hm[9]=a21; hm[10]=a22; hm[11]=a23;
        hm[12]=a30; hm[13]=a31; hm[14]=a32; hm[15]=a33;
        yv[0]=y0; yv[1]=y1; yv[2]=y2; yv[3]=y3;
        pinv_slow(hm, yv, xo);
        v0=xo[0]; v1=xo[1]; v2=xo[2]; v3=xo[3];
    }
    g_xls[i] = make_float4(__saturatef(v0), __saturatef(v1),
                           __saturatef(v2), __saturatef(v3));
}

// ================= Kernel B: MLP on MMA (R12 + unroll-2 chunk loop) =========
__global__ __launch_bounds__(NTHREADS, 4)
void matrixmlp_hmma(const float* __restrict__ x,
                    const float* __restrict__ W1, const float* __restrict__ b1,
                    const float* __restrict__ W2, const float* __restrict__ b2,
                    const float* __restrict__ W3, const float* __restrict__ b3,
                    float* __restrict__ out, int ntiles)
{
    extern __shared__ char sm[];
    uint32_t* w1f = (uint32_t*)(sm + O_W1F);
    uint32_t* w2f = (uint32_t*)(sm + O_W2F);
    float2*   b1p = (float2*)(sm + O_B1P);
    float2*   b2p = (float2*)(sm + O_B2P);
    uint32_t* w3f = (uint32_t*)(sm + O_W3F);
    float4*   b3s = (float4*)(sm + O_B3);

    const int tid  = threadIdx.x;
    const int lane = tid & 31;
    const int wid  = tid >> 5;
    const int q    = lane & 3;
    const int g    = lane >> 2;

    float* xls = (float*)(sm + O_XLS + wid * 512);         // [32][4]

    // ---- stage weights ----
    for (int i = tid; i < 3072; i += NTHREADS) {           // W1 tf32 k8 frags
        int e = i & 1, ln = (i >> 1) & 31, fi = i >> 6;
        int kt = fi >> 4, nt = fi & 15;
        int kk = 8 * kt + (ln & 3) + 4 * e, nn = 8 * nt + (ln >> 2);
        w1f[(fi << 6) + ((ln << 1) | e)] = f2tf(W1[kk * 128 + nn]);
    }
    for (int i = tid; i < 4096; i += NTHREADS) {           // W2 bf16 k16 frags
        int e = i & 1, ln = (i >> 1) & 31, fi = i >> 6;
        int kt = fi >> 3, nt = fi & 7;
        int k0 = 16 * kt + 2 * (ln & 3) + 8 * e, nn = 8 * nt + (ln >> 2);
        w2f[(fi << 6) + ((ln << 1) | e)] =
            packbf(W2[k0 * 64 + nn], W2[(k0 + 1) * 64 + nn]);
    }
    for (int i = tid; i < 256; i += NTHREADS) {            // W3 bf16 k16 frags (N=8 pad)
        int e = i & 1, ln = (i >> 1) & 31, fi = i >> 6;
        int k0 = 16 * fi + 2 * (ln & 3) + 8 * e, nn = ln >> 2;
        float lo = (nn < 4) ? W3[k0 * 4 + nn] : 0.0f;
        float hi = (nn < 4) ? W3[(k0 + 1) * 4 + nn] : 0.0f;
        w3f[(fi << 6) + ((ln << 1) | e)] = packbf(lo, hi);
    }
    for (int i = tid; i < 512; i += NTHREADS) {            // b1 pairs
        int ln = i & 31, ntg = i >> 5, qq = ln & 3;
        b1p[i] = make_float2(b1[8 * ntg + 2 * qq], b1[8 * ntg + 2 * qq + 1]);
    }
    for (int i = tid; i < 256; i += NTHREADS) {            // b2 pairs
        int ln = i & 31, nt = i >> 5, qq = ln & 3;
        b2p[i] = make_float2(b2[8 * nt + 2 * qq], b2[8 * nt + 2 * qq + 1]);
    }
    if (tid == 0) *b3s = *(const float4*)b3;
    __syncthreads();

    const float4 b3r = *b3s;

    for (int tile = blockIdx.x; tile < ntiles; tile += gridDim.x) {
        const int sample = tile * TILE + tid;

        const float4 xv4 = g_xls[sample];
        *(float4*)&xls[lane * 4] = xv4;
        __syncwarp();

        // ---- A0 tf32 fragments [2 Mtiles][3 Ktiles][4] ----
        const float* xg = x + (size_t)(tile * TILE + wid * 32) * 20;
        uint32_t A0[2][3][4];
#pragma unroll
        for (int m = 0; m < 2; m++) {
            const int r0 = 16 * m + g, r1 = r0 + 8;
#pragma unroll
            for (int kt = 0; kt < 2; kt++) {
                A0[m][kt][0] = f2tf(xg[r0 * 20 + 8 * kt + q]);
                A0[m][kt][1] = f2tf(xg[r1 * 20 + 8 * kt + q]);
                A0[m][kt][2] = f2tf(xg[r0 * 20 + 8 * kt + q + 4]);
                A0[m][kt][3] = f2tf(xg[r1 * 20 + 8 * kt + q + 4]);
            }
            A0[m][2][0] = f2tf(xg[r0 * 20 + 16 + q]);
            A0[m][2][1] = f2tf(xg[r1 * 20 + 16 + q]);
            A0[m][2][2] = f2tf(xls[r0 * 4 + q]);
            A0[m][2][3] = f2tf(xls[r1 * 4 + q]);
        }
        __syncwarp();

        // ---- layers 1+2: tf32 MMA -> in-register bf16 A-frag -> bf16 MMA ----
        float C2[2][8][4];
#pragma unroll
        for (int nt = 0; nt < 8; nt++) {
            const float2 bb = b2p[nt * 32 + lane];
#pragma unroll
            for (int m = 0; m < 2; m++) {
                C2[m][nt][0] = bb.x; C2[m][nt][1] = bb.y;
                C2[m][nt][2] = bb.x; C2[m][nt][3] = bb.y;
            }
        }

#pragma unroll 2
        for (int c = 0; c < 8; c++) {
            const float2 bb0 = b1p[(2 * c) * 32 + lane];
            const float2 bb1 = b1p[(2 * c + 1) * 32 + lane];
            float C1[2][2][4];
#pragma unroll
            for (int m = 0; m < 2; m++) {
                C1[m][0][0] = bb0.x; C1[m][0][1] = bb0.y;
                C1[m][0][2] = bb0.x; C1[m][0][3] = bb0.y;
                C1[m][1][0] = bb1.x; C1[m][1][1] = bb1.y;
                C1[m][1][2] = bb1.x; C1[m][1][3] = bb1.y;
            }

#pragma unroll
            for (int kt = 0; kt < 3; kt++) {
#pragma unroll
                for (int t = 0; t < 2; t++) {
                    uint2 b = *(const uint2*)
                        &w1f[((kt * 16 + 2 * c + t) << 6) + (lane << 1)];
                    mma_tf32(C1[0][t], A0[0][kt], b.x, b.y);
                    mma_tf32(C1[1][t], A0[1][kt], b.x, b.y);
                }
            }

            uint32_t af[2][4];
#pragma unroll
            for (int m = 0; m < 2; m++) {
                af[m][0] = packbf(fmaxf(C1[m][0][0], 0.0f), fmaxf(C1[m][0][1], 0.0f));
                af[m][1] = packbf(fmaxf(C1[m][0][2], 0.0f), fmaxf(C1[m][0][3], 0.0f));
                af[m][2] = packbf(fmaxf(C1[m][1][0], 0.0f), fmaxf(C1[m][1][1], 0.0f));
                af[m][3] = packbf(fmaxf(C1[m][1][2], 0.0f), fmaxf(C1[m][1][3], 0.0f));
            }

#pragma unroll
            for (int nt = 0; nt < 8; nt++) {
                uint2 b = *(const uint2*)&w2f[((c * 8 + nt) << 6) + (lane << 1)];
                mma_bf16(C2[0][nt], af[0], b.x, b.y);
                mma_bf16(C2[1][nt], af[1], b.x, b.y);
            }
        }

        // ---- layer3 on MMA: relu(C2) -> bf16 A-frags -> m16n8k16, N=8 pad ----
        float C3[2][4];
#pragma unroll
        for (int m = 0; m < 2; m++)
#pragma unroll
            for (int r = 0; r < 4; r++) C3[m][r] = 0.0f;

#pragma unroll
        for (int kt = 0; kt < 4; kt++) {
            uint32_t a3[2][4];
#pragma unroll
            for (int m = 0; m < 2; m++) {
                a3[m][0] = packbf(fmaxf(C2[m][2 * kt][0], 0.0f),
                                  fmaxf(C2[m][2 * kt][1], 0.0f));
                a3[m][1] = packbf(fmaxf(C2[m][2 * kt][2], 0.0f),
                                  fmaxf(C2[m][2 * kt][3], 0.0f));
                a3[m][2] = packbf(fmaxf(C2[m][2 * kt + 1][0], 0.0f),
                                  fmaxf(C2[m][2 * kt + 1][1], 0.0f));
                a3[m][3] = packbf(fmaxf(C2[m][2 * kt + 1][2], 0.0f),
                                  fmaxf(C2[m][2 * kt + 1][3], 0.0f));
            }
            uint2 b = *(const uint2*)&w3f[(kt << 6) + (lane << 1)];
            mma_bf16(C3[0], a3[0], b.x, b.y);
            mma_bf16(C3[1], a3[1], b.x, b.y);
        }

        // ---- epilogue: q<2 lanes hold real cols (2q, 2q+1 of 0..3) ----
        if (q < 2) {
            const float b3a = (q == 0) ? b3r.x : b3r.z;
            const float b3b = (q == 0) ? b3r.y : b3r.w;
            const int base = tile * TILE + wid * 32;
#pragma unroll
            for (int m = 0; m < 2; m++) {
                const int rA = 16 * m + g, rB = rA + 8;
                const float2 xA = *(const float2*)&xls[rA * 4 + 2 * q];
                float2 oA;
                oA.x = __saturatef(xA.x + C3[m][0] + b3a);
                oA.y = __saturatef(xA.y + C3[m][1] + b3b);
                ((float2*)out)[(size_t)(base + rA) * 2 + q] = oA;
                const float2 xB = *(const float2*)&xls[rB * 4 + 2 * q];
                float2 oB;
                oB.x = __saturatef(xB.x + C3[m][2] + b3a);
                oB.y = __saturatef(xB.y + C3[m][3] + b3b);
                ((float2*)out)[(size_t)(base + rB) * 2 + q] = oB;
            }
        }
        __syncwarp();   // xls reads done before next iteration overwrites
    }
}

extern "C" void kernel_launch(void* const* d_in, const int* in_sizes, int n_in,
                              void* d_out, int out_size)
{
    const float* x  = (const float*)d_in[0];
    const float* W1 = (const float*)d_in[1];
    const float* b1 = (const float*)d_in[2];
    const float* W2 = (const float*)d_in[3];
    const float* b2 = (const float*)d_in[4];
    const float* W3 = (const float*)d_in[5];
    const float* b3 = (const float*)d_in[6];
    float* out = (float*)d_out;

    const int nsamples = in_sizes[0] / 20;
    const int ntiles = nsamples / 128;           // 4096

    // Kernel A: x_ls into scratch (R12 best config)
    xls_kernel<<<(nsamples + 255) / 256, 256>>>(x, nsamples);

    // Kernel B: MLP, 4 CTAs/SM persistent
    int grid = 4 * 148;
    if (grid > ntiles) grid = ntiles;
    cudaFuncSetAttribute(matrixmlp_hmma,
                         cudaFuncAttributeMaxDynamicSharedMemorySize, SMEM_DYN);
    matrixmlp_hmma<<<grid, NTHREADS, SMEM_DYN>>>(x, W1, b1, W2, b2, W3, b3, out, ntiles);
}